// round 16
// baseline (speedup 1.0000x reference)
#include <cuda_runtime.h>

#define NQ    12
#define DIMN  4096
#define NGEN  2

typedef unsigned long long u64;

// fused 2x2 gate tables: [gen][layer(1,2)][wire 0..11][8]
// per gate: P00,Q00, P01,Q01, P10,Q10, P11,Q11  (P=(x,x), Q=(-y,y) packed)
__constant__ u64 cG[NGEN * 2 * NQ * 8];
__device__   u64 g_stage[NGEN * 2 * NQ * 8];

// ---------------- packed f32x2 helpers ----------------
__device__ __forceinline__ u64 pk(float lo, float hi){
    u64 r; asm("mov.b64 %0, {%1, %2};" : "=l"(r) : "f"(lo), "f"(hi)); return r;
}
__device__ __forceinline__ void upk(u64 v, float& lo, float& hi){
    asm("mov.b64 {%0, %1}, %2;" : "=f"(lo), "=f"(hi) : "l"(v));
}
__device__ __forceinline__ u64 f2mul(u64 a, u64 b){
    u64 d; asm("mul.rn.f32x2 %0, %1, %2;" : "=l"(d) : "l"(a), "l"(b)); return d;
}
__device__ __forceinline__ u64 f2fma(u64 a, u64 b, u64 c){
    u64 d; asm("fma.rn.f32x2 %0, %1, %2, %3;" : "=l"(d) : "l"(a), "l"(b), "l"(c)); return d;
}
__device__ __forceinline__ u64 swapp(u64 v){          // (x,y) -> (y,x)
    float lo, hi; upk(v, lo, hi); return pk(hi, lo);
}

// scalar complex helper (setup phases only)
__device__ __forceinline__ float2 cmul(float2 a, float2 b){
    return make_float2(fmaf(a.x, b.x, -(a.y * b.y)), fmaf(a.x, b.y, a.y * b.x));
}

// CNOT ring permutation, closed form:
// j0 = i ^ ((i&1)<<11); out = j0 ^ (j0>>1)
__device__ __forceinline__ int perm_src(int i){
    int j0 = i ^ ((i & 1) << 11);
    return j0 ^ (j0 >> 1);
}

// bank swizzle for 8-amp blocked layouts (verified conflict-free for all rounds)
__device__ __forceinline__ int swz8(int i){ return i ^ ((i >> 3) & 15); }

__device__ __forceinline__ u64 ld64(const float2* p){ return *reinterpret_cast<const u64*>(p); }
__device__ __forceinline__ void st64(float2* p, u64 v){ *reinterpret_cast<u64*>(p) = v; }

// ---- single-qubit 2x2 complex gate on register bit P of an 8-amp block ----
// coefficients from __constant__ (warp-uniform -> UR operands -> FFMA2 @ rt=2)
template<int P>
__device__ __forceinline__ void gate1(u64* a, int cb){
    const u64 g0 = cG[cb + 0], h0 = cG[cb + 1];
    const u64 g1 = cG[cb + 2], h1 = cG[cb + 3];
    const u64 g2 = cG[cb + 4], h2 = cG[cb + 5];
    const u64 g3 = cG[cb + 6], h3 = cG[cb + 7];
#pragma unroll
    for (int m = 0; m < 4; ++m) {
        const int i0 = ((m >> P) << (P + 1)) | (m & ((1 << P) - 1));
        const int i1 = i0 | (1 << P);
        u64 A0 = a[i0], A1 = a[i1];
        u64 S0 = swapp(A0), S1 = swapp(A1);
        a[i0] = f2fma(h1, S1, f2fma(g1, A1, f2fma(h0, S0, f2mul(g0, A0))));
        a[i1] = f2fma(h3, S1, f2fma(g3, A1, f2fma(h2, S0, f2mul(g2, A0))));
    }
}
// 3 single-qubit gates (wires w..w+2) on an 8-amp block, bits 2..0 <-> wires
__device__ __forceinline__ void gate3(u64* a, int cbL, int w){
    gate1<2>(a, cbL + (w    ) * 8);
    gate1<1>(a, cbL + (w + 1) * 8);
    gate1<0>(a, cbL + (w + 2) * 8);
}

// compute the fused M = RY*RX*RZ 2x2 for 3 angles
__device__ __forceinline__ void fuse3(const float* __restrict__ wp,
                                      float2& M00, float2& M01, float2& M10, float2& M11){
    float s1, c1, s2, c2, s3, c3;
    sincosf(0.5f * wp[0], &s1, &c1);
    sincosf(0.5f * wp[1], &s2, &c2);
    sincosf(0.5f * wp[2], &s3, &c3);
    float2 A00 = make_float2( c2 * c1, -c2 * s1);
    float2 A01 = make_float2( s2 * s1, -s2 * c1);
    float2 A10 = make_float2(-s2 * s1, -s2 * c1);
    float2 A11 = make_float2( c2 * c1,  c2 * s1);
    M00 = make_float2(c3*A00.x - s3*A10.x, c3*A00.y - s3*A10.y);
    M01 = make_float2(c3*A01.x - s3*A11.x, c3*A01.y - s3*A11.y);
    M10 = make_float2(s3*A00.x + c3*A10.x, s3*A00.y + c3*A10.y);
    M11 = make_float2(s3*A01.x + c3*A11.x, s3*A01.y + c3*A11.y);
}

// rounds B, C, D on a given buffer (B needs full barrier before; C->D warp-private)
__device__ __forceinline__ void roundsBCD(float2* st, int cbL, int tid){
    // ===== round B: bits 8..6 (wires 3..5) =====
    {
        const int base = ((tid >> 6) << 9) | (tid & 63);
        u64 a[8];
#pragma unroll
        for (int k = 0; k < 8; ++k)
            a[k] = ld64(&st[swz8(base | (k << 6))]);
        gate3(a, cbL, 3);
#pragma unroll
        for (int k = 0; k < 8; ++k)
            st64(&st[swz8(base | (k << 6))], a[k]);
    }
    __syncthreads();           // B->C is cross-warp

    // ===== round C: bits 5..3 (wires 6..8) =====
    {
        const int base = ((tid >> 3) << 6) | (tid & 7);
        u64 a[8];
#pragma unroll
        for (int k = 0; k < 8; ++k)
            a[k] = ld64(&st[swz8(base | (k << 3))]);
        gate3(a, cbL, 6);
#pragma unroll
        for (int k = 0; k < 8; ++k)
            st64(&st[swz8(base | (k << 3))], a[k]);
    }
    __syncwarp();              // C->D is warp-private

    // ===== round D: bits 2..0 (wires 9..11) =====
    {
        const int base = tid << 3;
        u64 a[8];
#pragma unroll
        for (int k = 0; k < 8; ++k)
            a[k] = ld64(&st[swz8(base | k)]);
        gate3(a, cbL, 9);
#pragma unroll
        for (int k = 0; k < 8; ++k)
            st64(&st[swz8(base | k)], a[k]);
    }
}

// ---------------- quantum circuit kernel ----------------
// grid: (4096 batch, 2 gen), block: 512 threads, 8 amps/thread.
// 2 CTAs/SM = 8 warps/SMSP; ~45 live regs (64 cap safe); ping-pong buffers.
__global__ void __launch_bounds__(512, 2)
qsim_kernel(const float* __restrict__ x,
            const float* __restrict__ qp,
            float* __restrict__ out)
{
    __shared__ float2 st0[4096];                   // statevector buffer 0
    __shared__ float2 st1[4096];                   // statevector buffer 1
    __shared__ float2 v[12][2];                    // layer-0 column vectors (per-sample)
    __shared__ float2 lowtab[16];                  // product over wires 8..11
    __shared__ float2 hitab[256];                  // product over wires 0..7

    const int tid = threadIdx.x;
    const int cb0 = (int)blockIdx.y * (2 * NQ * 8);   // layer-1 gate base
    const int cb1 = cb0 + NQ * 8;                      // layer-2 gate base

    // ---- phase 1: layer-0 fused column vectors (threads 0..11) ----
    if (tid < 12) {
        const int q = tid;
        float2 M00, M01, M10, M11;
        fuse3(qp + blockIdx.y * 108 + q * 3, M00, M01, M10, M11);
        float sx, cx;
        sincosf(0.5f * x[blockIdx.x * NQ + q], &sx, &cx);
        v[q][0] = make_float2(M00.x*cx + M01.x*sx, M00.y*cx + M01.y*sx);
        v[q][1] = make_float2(M10.x*cx + M11.x*sx, M10.y*cx + M11.y*sx);
    }
    __syncthreads();

    // ---- phase 2: low/high product tables ----
    if (tid < 16) {
        lowtab[tid] = cmul(cmul(v[8][(tid >> 3) & 1], v[ 9][(tid >> 2) & 1]),
                           cmul(v[10][(tid >> 1) & 1], v[11][ tid       & 1]));
    }
    if (tid < 256) {
        float2 hv = v[0][(tid >> 7) & 1];
#pragma unroll
        for (int y = 1; y < 8; ++y)
            hv = cmul(hv, v[y][(tid >> (7 - y)) & 1]);
        hitab[tid] = hv;
    }
    __syncthreads();

    // ================== layer 1 (on buffer 0) ==================
    // round A: init (product state + layer-0 CNOT perm fused), bits 11..9
    {
        u64 a[8];
#pragma unroll
        for (int k = 0; k < 8; ++k) {
            const int j = perm_src((k << 9) | tid);
            float2 val = cmul(hitab[j >> 4], lowtab[j & 15]);
            a[k] = pk(val.x, val.y);
        }
        gate3(a, cb0, 0);
#pragma unroll
        for (int k = 0; k < 8; ++k)
            st64(&st0[swz8((k << 9) | tid)], a[k]);
    }
    __syncthreads();           // A->B cross-warp

    roundsBCD(st0, cb0, tid);
    __syncthreads();           // layer-2 gather reads cross-warp

    // ===== layer 2 round A: gather st0 (perm fused) -> gates -> st1 =====
    {
        u64 a[8];
#pragma unroll
        for (int k = 0; k < 8; ++k)
            a[k] = ld64(&st0[swz8(perm_src((k << 9) | tid))]);
        gate3(a, cb1, 0);
#pragma unroll
        for (int k = 0; k < 8; ++k)
            st64(&st1[swz8((k << 9) | tid)], a[k]);
    }
    __syncthreads();

    roundsBCD(st1, cb1, tid);
    __syncthreads();           // readout gathers cross-warp

    // ---- probabilities, with layer-2 CNOT-ring perm fused into the read ----
    float* orow = out + (((size_t)blockIdx.x * NGEN + blockIdx.y) << 12);
#pragma unroll
    for (int k = 0; k < 8; ++k) {
        const int i = (k << 9) | tid;
        float2 a = st1[swz8(perm_src(i))];
        orow[i] = fmaf(a.x, a.x, a.y * a.y);
    }
}

// ---------------- linear layer + gate precompute fold-in ----------------
// (x @ W^T + b) * 5, tiled; 4 cols/thread. Block (0,0) threads 0..47 also
// compute the 48 fused circuit gates into g_stage (removes a serial launch).
#define LB 64
__global__ void __launch_bounds__(256)
linear_kernel(const float* __restrict__ x,
              const float* __restrict__ lw,
              const float* __restrict__ lb,
              const float* __restrict__ qp,
              float* __restrict__ out)
{
    __shared__ float4 xs4[LB][3];
    const int tid = threadIdx.x;
    const int d   = blockIdx.x * 1024 + tid * 4;
    const int b0  = blockIdx.y * LB;

    // gate precompute on one block's first 48 threads
    if (blockIdx.x == 0 && blockIdx.y == 0 && tid < 48) {
        const int gen = tid / 24, l = 1 + (tid % 24) / 12, q = tid % 12;
        float2 M00, M01, M10, M11;
        fuse3(qp + gen * 108 + l * 36 + q * 3, M00, M01, M10, M11);
        u64* gb = g_stage + (((gen * 2) + (l - 1)) * NQ + q) * 8;
        gb[0] = pk(M00.x, M00.x);  gb[1] = pk(-M00.y, M00.y);
        gb[2] = pk(M01.x, M01.x);  gb[3] = pk(-M01.y, M01.y);
        gb[4] = pk(M10.x, M10.x);  gb[5] = pk(-M10.y, M10.y);
        gb[6] = pk(M11.x, M11.x);  gb[7] = pk(-M11.y, M11.y);
    }

    // x rows are 12 floats = 3 float4, 16B-aligned (48B rows)
    const float4* xsrc = reinterpret_cast<const float4*>(x + (size_t)b0 * NQ);
    for (int t = tid; t < LB * 3; t += 256)
        xs4[t / 3][t % 3] = xsrc[t];
    __syncthreads();

    // weights & bias for 4 columns, pre-scaled by TEMPERATURE=5
    float wr[4][12];
    float bias[4];
#pragma unroll
    for (int c = 0; c < 4; ++c) {
        const float4* wp = reinterpret_cast<const float4*>(lw + (size_t)(d + c) * NQ);
#pragma unroll
        for (int j = 0; j < 3; ++j) {
            float4 wv = wp[j];
            wr[c][j*4+0] = wv.x * 5.0f; wr[c][j*4+1] = wv.y * 5.0f;
            wr[c][j*4+2] = wv.z * 5.0f; wr[c][j*4+3] = wv.w * 5.0f;
        }
        bias[c] = lb[d + c] * 5.0f;
    }

#pragma unroll 2
    for (int bb = 0; bb < LB; ++bb) {
        float4 x0 = xs4[bb][0], x1 = xs4[bb][1], x2 = xs4[bb][2];
        float xl[12] = { x0.x, x0.y, x0.z, x0.w, x1.x, x1.y, x1.z, x1.w,
                         x2.x, x2.y, x2.z, x2.w };
        float4 o;
        float* op = &o.x;
#pragma unroll
        for (int c = 0; c < 4; ++c) {
            float acc = bias[c];
#pragma unroll
            for (int j = 0; j < 12; ++j) acc = fmaf(xl[j], wr[c][j], acc);
            op[c] = acc;
        }
        *reinterpret_cast<float4*>(&out[(size_t)(b0 + bb) * DIMN + d]) = o;
    }
}

extern "C" void kernel_launch(void* const* d_in, const int* in_sizes, int n_in,
                              void* d_out, int out_size)
{
    const float* x  = (const float*)d_in[0];   // (4096, 12)
    const float* qp = (const float*)d_in[1];   // (2, 108)
    const float* lw = (const float*)d_in[2];   // (4096, 12)
    const float* lb = (const float*)d_in[3];   // (4096,)
    float* out = (float*)d_out;                // probs (4096,8192) then converted_x (4096,4096)

    // 1. linear (also computes fused gates into g_stage on block 0)
    dim3 lgrid(DIMN / 1024, 4096 / LB);
    linear_kernel<<<lgrid, 256>>>(x, lw, lb, qp, out + (size_t)4096 * (NGEN * DIMN));

    // 2. stage gates into __constant__ (D2D memcpy node, graph-capturable)
    void* sp = nullptr;
    cudaGetSymbolAddress(&sp, g_stage);
    cudaMemcpyToSymbolAsync(cG, sp, sizeof(u64) * NGEN * 2 * NQ * 8, 0,
                            cudaMemcpyDeviceToDevice, 0);

    // 3. quantum circuit
    dim3 grid(4096, NGEN);
    qsim_kernel<<<grid, 512>>>(x, qp, out);
}

// round 17
// speedup vs baseline: 1.2886x; 1.2886x over previous
#include <cuda_runtime.h>

#define NQ    12
#define DIMN  4096
#define NGEN  2

typedef unsigned long long u64;

// constant layout (512 u64 = 4KB):
//  [0..383]  gates [gen][layer 1|2][wire 0..11][8]:
//            pu=(zg.x,zg.x), qu=(-zg.y,zg.y), pc=(c,c), pns=(-s,-s), ps=(s,s), pad*3
//            (mixed gate = R(beta)*diag(1,zg); alpha deferred; global phase dropped)
//  per gen at 384+gen*64:
//   +0..15   AH : layer-1 alpha phases, wires 0-3  (state bits 11-8), packed float2
//   +16..31  AM : wires 4-7  (state bits 7-4), packed float2
//   +32..63  ALP: wires 8-11 (state bits 3-0), 16 pairs (P=(x,x), Q=(-y,y))
#define CG_SIZE 512
__constant__ u64 cG[CG_SIZE];
__device__   u64 g_stage[CG_SIZE];

// ---------------- packed f32x2 helpers ----------------
__device__ __forceinline__ u64 pk(float lo, float hi){
    u64 r; asm("mov.b64 %0, {%1, %2};" : "=l"(r) : "f"(lo), "f"(hi)); return r;
}
__device__ __forceinline__ void upk(u64 v, float& lo, float& hi){
    asm("mov.b64 {%0, %1}, %2;" : "=f"(lo), "=f"(hi) : "l"(v));
}
__device__ __forceinline__ u64 f2mul(u64 a, u64 b){
    u64 d; asm("mul.rn.f32x2 %0, %1, %2;" : "=l"(d) : "l"(a), "l"(b)); return d;
}
__device__ __forceinline__ u64 f2fma(u64 a, u64 b, u64 c){
    u64 d; asm("fma.rn.f32x2 %0, %1, %2, %3;" : "=l"(d) : "l"(a), "l"(b), "l"(c)); return d;
}
__device__ __forceinline__ u64 swapp(u64 v){          // (x,y) -> (y,x)
    float lo, hi; upk(v, lo, hi); return pk(hi, lo);
}

// scalar complex helper (setup phases only)
__device__ __forceinline__ float2 cmul(float2 a, float2 b){
    return make_float2(fmaf(a.x, b.x, -(a.y * b.y)), fmaf(a.x, b.y, a.y * b.x));
}

// CNOT ring permutation, closed form:
// j0 = i ^ ((i&1)<<11); out = j0 ^ (j0>>1)
__device__ __forceinline__ int perm_src(int i){
    int j0 = i ^ ((i & 1) << 11);
    return j0 ^ (j0 >> 1);
}

// bank swizzle for the state arrays
__device__ __forceinline__ int swz(int i){ return i ^ ((i >> 4) & 15); }

__device__ __forceinline__ u64 ld64(const float2* p){ return *reinterpret_cast<const u64*>(p); }
__device__ __forceinline__ void st64(float2* p, u64 v){ *reinterpret_cast<u64*>(p) = v; }

// ---- mixed gate R(beta)*diag(1,zg) on register bit P of a 16-amp block ----
// out0 = c*A0 - s*(zg*A1);  out1 = s*A0 + c*(zg*A1)
// coefficients from __constant__ (warp-uniform -> UR operands -> rt=2 FFMA2)
template<int P>
__device__ __forceinline__ void rot1(u64* a, int cb){
    const u64 pu  = cG[cb + 0], qu = cG[cb + 1];
    const u64 pc  = cG[cb + 2], pns = cG[cb + 3], ps = cG[cb + 4];
#pragma unroll
    for (int m = 0; m < 8; ++m) {
        const int i0 = ((m >> P) << (P + 1)) | (m & ((1 << P) - 1));
        const int i1 = i0 | (1 << P);
        u64 A0 = a[i0], A1 = a[i1];
        u64 t = f2fma(qu, swapp(A1), f2mul(pu, A1));   // zg * A1
        a[i0] = f2fma(pns, t, f2mul(pc, A0));
        a[i1] = f2fma(pc,  t, f2mul(ps, A0));
    }
}
// 4 mixed gates (wires w..w+3) on a 16-amp block, block bits 3..0 <-> wires
__device__ __forceinline__ void rot4(u64* a, int cbL, int w){
    rot1<3>(a, cbL + (w    ) * 8);
    rot1<2>(a, cbL + (w + 1) * 8);
    rot1<1>(a, cbL + (w + 2) * 8);
    rot1<0>(a, cbL + (w + 3) * 8);
}

// compute the fused M = RY*RX*RZ 2x2 for 3 angles
__device__ __forceinline__ void fuse3(const float* __restrict__ wp,
                                      float2& M00, float2& M01, float2& M10, float2& M11){
    float s1, c1, s2, c2, s3, c3;
    sincosf(0.5f * wp[0], &s1, &c1);
    sincosf(0.5f * wp[1], &s2, &c2);
    sincosf(0.5f * wp[2], &s3, &c3);
    float2 A00 = make_float2( c2 * c1, -c2 * s1);
    float2 A01 = make_float2( s2 * s1, -s2 * c1);
    float2 A10 = make_float2(-s2 * s1, -s2 * c1);
    float2 A11 = make_float2( c2 * c1,  c2 * s1);
    M00 = make_float2(c3*A00.x - s3*A10.x, c3*A00.y - s3*A10.y);
    M01 = make_float2(c3*A01.x - s3*A11.x, c3*A01.y - s3*A11.y);
    M10 = make_float2(s3*A00.x + c3*A10.x, s3*A00.y + c3*A10.y);
    M11 = make_float2(s3*A01.x + c3*A11.x, s3*A01.y + c3*A11.y);
}

// rounds B and C on a given buffer; tbase >= 0 applies the deferred
// layer-1 alpha diagonal (per-thread const from AH*AM, per-amp from ALP)
__device__ __forceinline__ void roundsBC(float2* st, int cbL, int tid, int tbase){
    // ===== round B: state bits 7..4 (wires 4..7), warp-private slab =====
    {
        const int base = ((tid >> 4) << 8) | (tid & 15);
        u64 a[16];
#pragma unroll
        for (int q = 0; q < 4; ++q)
#pragma unroll
        for (int r = 0; r < 4; ++r)
            a[q*4 + r] = ld64(&st[swz(base + (q << 6) + (r << 4))]);
        rot4(a, cbL, 4);
#pragma unroll
        for (int q = 0; q < 4; ++q)
#pragma unroll
        for (int r = 0; r < 4; ++r)
            st64(&st[swz(base + (q << 6) + (r << 4))], a[q*4 + r]);
    }
    __syncwarp();              // B->C dependency is within-warp only

    // ===== round C: state bits 3..0 (wires 8..11), warp-private slab =====
    {
        const int base = tid << 4;
        const int sx4  = tid & 15;
        u64 a[16];
#pragma unroll
        for (int c = 0; c < 16; ++c)
            a[c] = ld64(&st[base | (c ^ sx4)]);
        rot4(a, cbL, 8);
        if (tbase >= 0) {
            // deferred layer-1 alpha diagonal
            float ahx, ahy, amx, amy;
            upk(cG[tbase + (tid >> 4)], ahx, ahy);
            upk(cG[tbase + 16 + (tid & 15)], amx, amy);
            const float tcx = fmaf(ahx, amx, -(ahy * amy));
            const float tcy = fmaf(ahx, amy, ahy * amx);
            const u64 tP = pk(tcx, tcx), tQ = pk(-tcy, tcy);
#pragma unroll
            for (int c = 0; c < 16; ++c) {
                u64 v = f2fma(tQ, swapp(a[c]), f2mul(tP, a[c]));
                const u64 pu = cG[tbase + 32 + 2*c], qu = cG[tbase + 33 + 2*c];
                a[c] = f2fma(qu, swapp(v), f2mul(pu, v));
            }
        }
#pragma unroll
        for (int c = 0; c < 16; ++c)
            st64(&st[base | (c ^ sx4)], a[c]);
    }
}

// ---------------- quantum circuit kernel ----------------
// grid: (4096 batch, 2 gen), block: 256 threads, 16 amps/thread.
// Ping-pong buffers; ZYZ-decomposed gates in __constant__; 3 CTAs/SM.
__global__ void __launch_bounds__(256, 3)
qsim_kernel(const float* __restrict__ x,
            const float* __restrict__ qp,
            float* __restrict__ out)
{
    __shared__ float2 st0[4096];                   // statevector buffer 0
    __shared__ float2 st1[4096];                   // statevector buffer 1
    __shared__ float2 v[12][2];                    // layer-0 column vectors (per-sample)
    __shared__ float2 lowtab[16];                  // product over wires 8..11
    __shared__ float2 hitab[256];                  // product over wires 0..7

    const int tid = threadIdx.x;
    const int cb0 = (int)blockIdx.y * (2 * NQ * 8);   // layer-1 gate base
    const int cb1 = cb0 + NQ * 8;                      // layer-2 gate base
    const int tb  = 384 + (int)blockIdx.y * 64;        // alpha table base

    // ---- phase 1: layer-0 fused column vectors (threads 0..11) ----
    if (tid < 12) {
        const int q = tid;
        float2 M00, M01, M10, M11;
        fuse3(qp + blockIdx.y * 108 + q * 3, M00, M01, M10, M11);
        float sx, cx;
        sincosf(0.5f * x[blockIdx.x * NQ + q], &sx, &cx);
        v[q][0] = make_float2(M00.x*cx + M01.x*sx, M00.y*cx + M01.y*sx);
        v[q][1] = make_float2(M10.x*cx + M11.x*sx, M10.y*cx + M11.y*sx);
    }
    __syncthreads();

    // ---- phase 2: low/high product tables ----
    if (tid < 16) {
        lowtab[tid] = cmul(cmul(v[8][(tid >> 3) & 1], v[ 9][(tid >> 2) & 1]),
                           cmul(v[10][(tid >> 1) & 1], v[11][ tid       & 1]));
    }
    {
        float2 hv = v[0][(tid >> 7) & 1];
#pragma unroll
        for (int y = 1; y < 8; ++y)
            hv = cmul(hv, v[y][(tid >> (7 - y)) & 1]);
        hitab[tid] = hv;
    }
    __syncthreads();

    // ================== layer 1 (on buffer 0) ==================
    // round A: init (product state + layer-0 CNOT perm fused) -> rotations -> st0
    {
        u64 a[16];
#pragma unroll
        for (int q = 0; q < 4; ++q)
#pragma unroll
        for (int r = 0; r < 4; ++r) {
            const int idx = tid + (q << 10) + (r << 8);
            const int j = perm_src(idx);
            float2 val = cmul(hitab[j >> 4], lowtab[j & 15]);
            a[q*4 + r] = pk(val.x, val.y);
        }
        rot4(a, cb0, 0);
#pragma unroll
        for (int q = 0; q < 4; ++q)
#pragma unroll
        for (int r = 0; r < 4; ++r)
            st64(&st0[swz(tid + (q << 10) + (r << 8))], a[q*4 + r]);
    }
    __syncthreads();           // round A stores visible to all warps

    roundsBC(st0, cb0, tid, tb);   // includes deferred layer-1 alpha diag
    __syncthreads();           // layer-2 gather reads cross-warp

    // ============ layer 2 (gather st0 -> store st1, no WAR barrier) ============
    {
        u64 a[16];
#pragma unroll
        for (int q = 0; q < 4; ++q)
#pragma unroll
        for (int r = 0; r < 4; ++r) {
            const int idx = tid + (q << 10) + (r << 8);
            a[q*4 + r] = ld64(&st0[swz(perm_src(idx))]);
        }
        rot4(a, cb1, 0);
#pragma unroll
        for (int q = 0; q < 4; ++q)
#pragma unroll
        for (int r = 0; r < 4; ++r)
            st64(&st1[swz(tid + (q << 10) + (r << 8))], a[q*4 + r]);
    }
    __syncthreads();

    roundsBC(st1, cb1, tid, -1);   // layer-2 alpha diag dropped (pure phases)
    __syncthreads();           // readout gathers cross-warp

    // ---- probabilities, with layer-2 CNOT-ring perm fused into the read ----
    float* orow = out + (((size_t)blockIdx.x * NGEN + blockIdx.y) << 12);
#pragma unroll
    for (int r = 0; r < 16; ++r) {
        const int i = tid + 256 * r;
        float2 a = st1[swz(perm_src(i))];
        orow[i] = fmaf(a.x, a.x, a.y * a.y);
    }
}

// ---------------- linear layer + ZYZ gate precompute fold-in ----------------
#define LB 64
__global__ void __launch_bounds__(256)
linear_kernel(const float* __restrict__ x,
              const float* __restrict__ lw,
              const float* __restrict__ lb,
              const float* __restrict__ qp,
              float* __restrict__ out)
{
    __shared__ float4 xs4[LB][3];
    __shared__ float2 salpha[NGEN][NQ];
    const int tid = threadIdx.x;
    const int d   = blockIdx.x * 1024 + tid * 4;
    const int b0  = blockIdx.y * LB;
    const bool prep = (blockIdx.x == 0 && blockIdx.y == 0);

    // ZYZ gate precompute on block (0,0) threads 0..47
    if (prep && tid < 48) {
        const int gen = tid / 24, l = 1 + (tid % 24) / 12, q = tid % 12;
        float2 M00, M01, M10, M11;
        fuse3(qp + gen * 108 + l * 36 + q * 3, M00, M01, M10, M11);
        const float c = sqrtf(M00.x*M00.x + M00.y*M00.y);
        const float s = sqrtf(M10.x*M10.x + M10.y*M10.y);
        const float tha = atan2f(M00.y, M00.x);
        const float thb = atan2f(M10.y, M10.x);
        const float al = thb - tha, ga = -tha - thb;
        float sg, cg2; sincosf(ga, &sg, &cg2);
        u64* gb = g_stage + (((gen * 2) + (l - 1)) * NQ + q) * 8;
        gb[0] = pk(cg2, cg2);   // pu
        gb[1] = pk(-sg, sg);    // qu
        gb[2] = pk(c, c);       // pc
        gb[3] = pk(-s, -s);     // pns
        gb[4] = pk(s, s);       // ps
        if (l == 1) {
            float sa, ca; sincosf(al, &sa, &ca);
            salpha[gen][q] = make_float2(ca, sa);
        }
    }

    // x rows are 12 floats = 3 float4, 16B-aligned (48B rows)
    const float4* xsrc = reinterpret_cast<const float4*>(x + (size_t)b0 * NQ);
    for (int t = tid; t < LB * 3; t += 256)
        xs4[t / 3][t % 3] = xsrc[t];
    __syncthreads();

    // alpha table build (block (0,0), threads 0..95), after salpha is visible
    if (prep && tid < 96) {
        const int gen = tid / 48, u = tid % 48, tbl = u / 16, vix = u % 16;
        float2 p = make_float2(1.f, 0.f);
#pragma unroll
        for (int k = 0; k < 4; ++k)
            if ((vix >> (3 - k)) & 1)
                p = cmul(p, salpha[gen][tbl * 4 + k]);
        u64* base = g_stage + 384 + gen * 64;
        if (tbl < 2) {
            base[tbl * 16 + vix] = pk(p.x, p.y);
        } else {
            base[32 + 2 * vix]     = pk(p.x, p.x);
            base[32 + 2 * vix + 1] = pk(-p.y, p.y);
        }
    }

    // weights & bias for 4 columns, pre-scaled by TEMPERATURE=5
    float wr[4][12];
    float bias[4];
#pragma unroll
    for (int c = 0; c < 4; ++c) {
        const float4* wp = reinterpret_cast<const float4*>(lw + (size_t)(d + c) * NQ);
#pragma unroll
        for (int j = 0; j < 3; ++j) {
            float4 wv = wp[j];
            wr[c][j*4+0] = wv.x * 5.0f; wr[c][j*4+1] = wv.y * 5.0f;
            wr[c][j*4+2] = wv.z * 5.0f; wr[c][j*4+3] = wv.w * 5.0f;
        }
        bias[c] = lb[d + c] * 5.0f;
    }

#pragma unroll 2
    for (int bb = 0; bb < LB; ++bb) {
        float4 x0 = xs4[bb][0], x1 = xs4[bb][1], x2 = xs4[bb][2];
        float xl[12] = { x0.x, x0.y, x0.z, x0.w, x1.x, x1.y, x1.z, x1.w,
                         x2.x, x2.y, x2.z, x2.w };
        float4 o;
        float* op = &o.x;
#pragma unroll
        for (int c = 0; c < 4; ++c) {
            float acc = bias[c];
#pragma unroll
            for (int j = 0; j < 12; ++j) acc = fmaf(xl[j], wr[c][j], acc);
            op[c] = acc;
        }
        *reinterpret_cast<float4*>(&out[(size_t)(b0 + bb) * DIMN + d]) = o;
    }
}

extern "C" void kernel_launch(void* const* d_in, const int* in_sizes, int n_in,
                              void* d_out, int out_size)
{
    const float* x  = (const float*)d_in[0];   // (4096, 12)
    const float* qp = (const float*)d_in[1];   // (2, 108)
    const float* lw = (const float*)d_in[2];   // (4096, 12)
    const float* lb = (const float*)d_in[3];   // (4096,)
    float* out = (float*)d_out;                // probs (4096,8192) then converted_x (4096,4096)

    // 1. linear (also computes ZYZ gates + alpha tables into g_stage on block 0)
    dim3 lgrid(DIMN / 1024, 4096 / LB);
    linear_kernel<<<lgrid, 256>>>(x, lw, lb, qp, out + (size_t)4096 * (NGEN * DIMN));

    // 2. stage gates into __constant__ (D2D memcpy node, graph-capturable)
    void* sp = nullptr;
    cudaGetSymbolAddress(&sp, g_stage);
    cudaMemcpyToSymbolAsync(cG, sp, sizeof(u64) * CG_SIZE, 0,
                            cudaMemcpyDeviceToDevice, 0);

    // 3. quantum circuit
    dim3 grid(4096, NGEN);
    qsim_kernel<<<grid, 256>>>(x, qp, out);
}